// round 2
// baseline (speedup 1.0000x reference)
#include <cuda_runtime.h>

#define POOL  7
#define NROI  1000
#define IMH   128
#define IMW   128
#define NC    512
#define NC4   (NC / 4)      // 128 float4 per pixel
#define NPOS  (NROI * POOL * POOL)   // 49000
#define NOUT4 (NPOS * NC4)           // 6,272,000 float4 outputs

struct __align__(16) Coord {
    int   i0;
    int   i1;
    float frac;
    float pad;
};

__device__ Coord d_cy[NROI * POOL];
__device__ Coord d_cx[NROI * POOL];

// ---------------------------------------------------------------------------
// Kernel A: per-ROI bilinear sample coordinates (matches reference numerics:
// rintf = round-half-even like jnp.round; __fdiv_rn for the /POOL grid).
// ---------------------------------------------------------------------------
__global__ void roi_coords_kernel(const float* __restrict__ roi)
{
    int n = blockIdx.x * blockDim.x + threadIdx.x;
    if (n >= NROI) return;

    float x = roi[n * 4 + 0];
    float y = roi[n * 4 + 1];
    float w = roi[n * 4 + 2];
    float h = roi[n * 4 + 3];

    const float inv_stride = 1.0f / 16.0f;   // STRIDE=16 is a power of 2: exact
    float r  = rintf((x - 0.5f * w) * inv_stride);
    float c  = rintf((y - 0.5f * h) * inv_stride);
    float wq = fmaxf(rintf(w * inv_stride), 1.0f);
    float hq = fmaxf(rintf(h * inv_stride), 1.0f);

#pragma unroll
    for (int p = 0; p < POOL; p++) {
        float g = __fdiv_rn((float)p + 0.5f, (float)POOL);

        // y axis (rows; start=c, size=hq, limit=IMH)
        {
            float s  = g * hq - 0.5f;
            s        = fminf(fmaxf(s, 0.0f), hq - 1.0f);
            float f0 = floorf(s);
            float fr = s - f0;
            float f1 = fminf(f0 + 1.0f, hq - 1.0f);
            int i0 = (int)fminf(fmaxf(c + f0, 0.0f), (float)(IMH - 1));
            int i1 = (int)fminf(fmaxf(c + f1, 0.0f), (float)(IMH - 1));
            Coord cd; cd.i0 = i0; cd.i1 = i1; cd.frac = fr; cd.pad = 0.0f;
            d_cy[n * POOL + p] = cd;
        }
        // x axis (cols; start=r, size=wq, limit=IMW)
        {
            float s  = g * wq - 0.5f;
            s        = fminf(fmaxf(s, 0.0f), wq - 1.0f);
            float f0 = floorf(s);
            float fr = s - f0;
            float f1 = fminf(f0 + 1.0f, wq - 1.0f);
            int i0 = (int)fminf(fmaxf(r + f0, 0.0f), (float)(IMW - 1));
            int i1 = (int)fminf(fmaxf(r + f1, 0.0f), (float)(IMW - 1));
            Coord cd; cd.i0 = i0; cd.i1 = i1; cd.frac = fr; cd.pad = 0.0f;
            d_cx[n * POOL + p] = cd;
        }
    }
}

// ---------------------------------------------------------------------------
// Kernel B: one thread per float4 of output. 128 consecutive threads share one
// (roi, py, px) position -> warp-uniform coord loads, fully coalesced float4
// gathers from 4 contiguous 2KB pixel rows, coalesced streaming store.
// ---------------------------------------------------------------------------
__global__ void __launch_bounds__(256)
roi_pool_kernel(const float4* __restrict__ feat, float4* __restrict__ out)
{
    int idx = blockIdx.x * blockDim.x + threadIdx.x;
    if (idx >= NOUT4) return;

    int t   = idx & (NC4 - 1);   // channel-quad within pixel
    int pos = idx >> 7;          // (roi, py, px), NC4 == 128

    int px  = pos % POOL;
    int tm  = pos / POOL;
    int py  = tm % POOL;
    int n   = tm / POOL;

    Coord cy = d_cy[n * POOL + py];
    Coord cx = d_cx[n * POOL + px];

    float ly = cy.frac, lx = cx.frac;
    float oy = 1.0f - ly, ox = 1.0f - lx;
    float w00 = oy * ox;
    float w01 = oy * lx;
    float w10 = ly * ox;
    float w11 = ly * lx;

    const float4* p00 = feat + (size_t)(cy.i0 * IMW + cx.i0) * NC4;
    const float4* p01 = feat + (size_t)(cy.i0 * IMW + cx.i1) * NC4;
    const float4* p10 = feat + (size_t)(cy.i1 * IMW + cx.i0) * NC4;
    const float4* p11 = feat + (size_t)(cy.i1 * IMW + cx.i1) * NC4;

    float4 a = p00[t];
    float4 b = p01[t];
    float4 c = p10[t];
    float4 d = p11[t];

    float4 o;
    o.x = fmaf(w00, a.x, fmaf(w01, b.x, fmaf(w10, c.x, w11 * d.x)));
    o.y = fmaf(w00, a.y, fmaf(w01, b.y, fmaf(w10, c.y, w11 * d.y)));
    o.z = fmaf(w00, a.z, fmaf(w01, b.z, fmaf(w10, c.z, w11 * d.z)));
    o.w = fmaf(w00, a.w, fmaf(w01, b.w, fmaf(w10, c.w, w11 * d.w)));

    out[idx] = o;
}

extern "C" void kernel_launch(void* const* d_in, const int* in_sizes, int n_in,
                              void* d_out, int out_size)
{
    // metadata order: image (8,388,608 fp32), RoI (4000 fp32). Be robust anyway.
    const float* image = (const float*)d_in[0];
    const float* roi   = (const float*)d_in[1];
    if (n_in >= 2 && in_sizes[0] == NROI * 4) {
        roi   = (const float*)d_in[0];
        image = (const float*)d_in[1];
    }

    roi_coords_kernel<<<(NROI + 255) / 256, 256>>>(roi);

    int grid = (NOUT4 + 255) / 256;   // 24500
    roi_pool_kernel<<<grid, 256>>>((const float4*)image, (float4*)d_out);
}

// round 6
// speedup vs baseline: 1.2216x; 1.2216x over previous
#include <cuda_runtime.h>

#define POOL  7
#define NROI  1000
#define IMH   128
#define IMW   128
#define NC    512
#define NC4   (NC / 4)                 // 128 float4 per pixel
#define NPOS  (NROI * POOL * POOL)     // 49000 positions
#define GROUPS_PER_BLOCK 4             // 4 positions per 256-thread block
#define NBLOCKS (NPOS / GROUPS_PER_BLOCK)  // 12250

struct PosInfo {
    int   o00, o01, o10, o11;   // pixel base offsets in float4 units
    float w00, w01, w10, w11;   // bilinear weights
};

// ---------------------------------------------------------------------------
// Fused kernel: each 64-thread group handles one (roi, py, px) position and
// produces 128 float4 (2 per thread, at t and t+64 -> warp-contiguous).
// Lane 0 of each group computes the bilinear coords/weights into shared.
// Numerics match jnp exactly: rintf (round-half-even), __fdiv_rn for /POOL.
// ---------------------------------------------------------------------------
__global__ void __launch_bounds__(256)
roi_pool_fused_kernel(const float4* __restrict__ feat,
                      const float*  __restrict__ roi,
                      float4*       __restrict__ out)
{
    __shared__ PosInfo sh[GROUPS_PER_BLOCK];

    int grp = threadIdx.x >> 6;                // 0..3
    int g   = threadIdx.x & 63;                // lane within group
    int pos = blockIdx.x * GROUPS_PER_BLOCK + grp;   // 0..48999

    if (g == 0) {
        int n   = pos / (POOL * POOL);
        int rem = pos - n * (POOL * POOL);
        int py  = rem / POOL;
        int px  = rem - py * POOL;

        float x = roi[n * 4 + 0];
        float y = roi[n * 4 + 1];
        float w = roi[n * 4 + 2];
        float h = roi[n * 4 + 3];

        const float inv_stride = 1.0f / 16.0f;     // exact (power of 2)
        float r  = rintf((x - 0.5f * w) * inv_stride);
        float c  = rintf((y - 0.5f * h) * inv_stride);
        float wq = fmaxf(rintf(w * inv_stride), 1.0f);
        float hq = fmaxf(rintf(h * inv_stride), 1.0f);

        // y axis (rows): start=c, size=hq, limit=IMH, sample index py
        float gy = __fdiv_rn((float)py + 0.5f, (float)POOL);
        float sy = gy * hq - 0.5f;
        sy       = fminf(fmaxf(sy, 0.0f), hq - 1.0f);
        float fy0 = floorf(sy);
        float ly  = sy - fy0;
        float fy1 = fminf(fy0 + 1.0f, hq - 1.0f);
        int iy0 = (int)fminf(fmaxf(c + fy0, 0.0f), (float)(IMH - 1));
        int iy1 = (int)fminf(fmaxf(c + fy1, 0.0f), (float)(IMH - 1));

        // x axis (cols): start=r, size=wq, limit=IMW, sample index px
        float gx = __fdiv_rn((float)px + 0.5f, (float)POOL);
        float sx = gx * wq - 0.5f;
        sx       = fminf(fmaxf(sx, 0.0f), wq - 1.0f);
        float fx0 = floorf(sx);
        float lx  = sx - fx0;
        float fx1 = fminf(fx0 + 1.0f, wq - 1.0f);
        int ix0 = (int)fminf(fmaxf(r + fx0, 0.0f), (float)(IMW - 1));
        int ix1 = (int)fminf(fmaxf(r + fx1, 0.0f), (float)(IMW - 1));

        float oy = 1.0f - ly, ox = 1.0f - lx;

        PosInfo pi;
        pi.o00 = (iy0 * IMW + ix0) * NC4;
        pi.o01 = (iy0 * IMW + ix1) * NC4;
        pi.o10 = (iy1 * IMW + ix0) * NC4;
        pi.o11 = (iy1 * IMW + ix1) * NC4;
        pi.w00 = oy * ox;
        pi.w01 = oy * lx;
        pi.w10 = ly * ox;
        pi.w11 = ly * lx;
        sh[grp] = pi;
    }
    __syncthreads();

    PosInfo pi = sh[grp];

    int t0 = g;        // quads 0..63   (warp-contiguous)
    int t1 = g + 64;   // quads 64..127 (warp-contiguous)

    float4 a0 = feat[pi.o00 + t0];
    float4 a1 = feat[pi.o00 + t1];
    float4 b0 = feat[pi.o01 + t0];
    float4 b1 = feat[pi.o01 + t1];
    float4 c0 = feat[pi.o10 + t0];
    float4 c1 = feat[pi.o10 + t1];
    float4 d0 = feat[pi.o11 + t0];
    float4 d1 = feat[pi.o11 + t1];

    float w00 = pi.w00, w01 = pi.w01, w10 = pi.w10, w11 = pi.w11;

    float4 o0, o1;
    o0.x = fmaf(w00, a0.x, fmaf(w01, b0.x, fmaf(w10, c0.x, w11 * d0.x)));
    o0.y = fmaf(w00, a0.y, fmaf(w01, b0.y, fmaf(w10, c0.y, w11 * d0.y)));
    o0.z = fmaf(w00, a0.z, fmaf(w01, b0.z, fmaf(w10, c0.z, w11 * d0.z)));
    o0.w = fmaf(w00, a0.w, fmaf(w01, b0.w, fmaf(w10, c0.w, w11 * d0.w)));
    o1.x = fmaf(w00, a1.x, fmaf(w01, b1.x, fmaf(w10, c1.x, w11 * d1.x)));
    o1.y = fmaf(w00, a1.y, fmaf(w01, b1.y, fmaf(w10, c1.y, w11 * d1.y)));
    o1.z = fmaf(w00, a1.z, fmaf(w01, b1.z, fmaf(w10, c1.z, w11 * d1.z)));
    o1.w = fmaf(w00, a1.w, fmaf(w01, b1.w, fmaf(w10, c1.w, w11 * d1.w)));

    long long obase = (long long)pos * NC4;
    __stcs(out + obase + t0, o0);
    __stcs(out + obase + t1, o1);
}

extern "C" void kernel_launch(void* const* d_in, const int* in_sizes, int n_in,
                              void* d_out, int out_size)
{
    const float* image = (const float*)d_in[0];
    const float* roi   = (const float*)d_in[1];
    if (n_in >= 2 && in_sizes[0] == NROI * 4) {   // robustness to input order
        roi   = (const float*)d_in[0];
        image = (const float*)d_in[1];
    }

    roi_pool_fused_kernel<<<NBLOCKS, 256>>>((const float4*)image, roi,
                                            (float4*)d_out);
}